// round 13
// baseline (speedup 1.0000x reference)
#include <cuda_runtime.h>

// AnchorLoss: sum over masked pairs of 1 - exp(-||(e_i+a_i)-(e_j+a_j)||^2 / 10)
// B=8, N=2048, D=2. Mandatory traffic: the 134MB int32 mask, read once
// (~19-20us floor at achievable HBM BW).
//
// R13: kill the wave-drain tail + per-item prologue cost (R12: DRAM flat at
// 70.6% despite +occ -> MLP saturated; remaining gap = tail/bubbles).
//  - items 16 rows x 128 cols (16384 items, ~2.2us) -> drain tail ~1us
//  - ROWS_PW(4) == DEPTH: whole warp-item prefetched in prologue; hot loop
//    has NO refill instructions
//  - persistent 1480 CTAs + atomic queue, sequential t with row-group fastest
//    -> consecutive items share (batch,slab): slab point constants CACHED
//       across items (rebuilt ~1/128 items)
//  - compute core unchanged: exponent = w_r + w_c + 2u_r u_c + 2v_r v_c,
//    pair = 2xFFMA+MUFU+ISETP+@P FADD; 2^(w_r) factored per row; row consts
//    via SHFL from lanes 0..3.

#define BATCH    8
#define NPTS     2048
#define THREADS  128
#define NWARPS   4
#define ROWS_IT  16                          // rows per item
#define ROWS_PW  4                           // rows per warp (== ring depth)
#define ITEMS    (BATCH * 16 * 128)          // 16384: b | slab | row-group

__device__ unsigned int g_ctr;

__global__ void __launch_bounds__(THREADS, 10) anchor_loss_kernel(
    const float* __restrict__ emb,
    const float* __restrict__ abscoords,
    const int*   __restrict__ mask,
    float*       __restrict__ out)
{
    __shared__ float    wsum[NWARPS];
    __shared__ unsigned s_t;

    const int warp = threadIdx.x >> 5;
    const int lane = threadIdx.x & 31;
    const float S = 0.37982354f;             // sqrt(log2(e)/10)

    float acc  = 0.0f;
    int   ckey = -1;                         // cached (batch,slab) key
    float u4[4], v4[4], w4[4];               // cached slab-point constants

    for (;;) {
        if (threadIdx.x == 0) s_t = atomicAdd(&g_ctr, 1u);
        __syncthreads();
        const unsigned t = s_t;
        __syncthreads();                     // s_t safely re-writable next iter
        if (t >= ITEMS) break;               // uniform across the block

        // t = b(3b) | slab(4b) | row-group(7b)  -> row-group fastest
        const int b    = (int)(t >> 11);
        const int slab = (int)((t >> 7) & 15);
        const int i0   = (int)(t & 127) * ROWS_IT;
        const int j0   = slab * 128;

        const float2* e2 = (const float2*)emb       + (size_t)b * NPTS;
        const float2* a2 = (const float2*)abscoords + (size_t)b * NPTS;

        // ---- FIRST: whole warp-item mask in flight (4 x LDG.128) ----
        const int iA = i0 + warp * ROWS_PW;
        const int4* mrow = reinterpret_cast<const int4*>(
            mask + ((size_t)b * NPTS + iA) * NPTS + j0) + lane;
        int4 mb[ROWS_PW];
        #pragma unroll
        for (int d = 0; d < ROWS_PW; d++)
            mb[d] = __ldcs(mrow + 512 * d);

        // ---- slab point constants: cached across items (same b,slab) ----
        const int key = (int)(t >> 7);
        if (key != ckey) {
            ckey = key;
            const float4* ee = reinterpret_cast<const float4*>(e2 + j0);
            const float4* aa = reinterpret_cast<const float4*>(a2 + j0);
            float4 ex0 = __ldg(ee + 2 * lane);
            float4 ex1 = __ldg(ee + 2 * lane + 1);
            float4 ax0 = __ldg(aa + 2 * lane);
            float4 ax1 = __ldg(aa + 2 * lane + 1);
            u4[0] = (ex0.x + ax0.x) * S;  v4[0] = (ex0.y + ax0.y) * S;
            u4[1] = (ex0.z + ax0.z) * S;  v4[1] = (ex0.w + ax0.w) * S;
            u4[2] = (ex1.x + ax1.x) * S;  v4[2] = (ex1.y + ax1.y) * S;
            u4[3] = (ex1.z + ax1.z) * S;  v4[3] = (ex1.w + ax1.w) * S;
            #pragma unroll
            for (int k = 0; k < 4; k++)
                w4[k] = -fmaf(u4[k], u4[k], v4[k] * v4[k]);
        }

        // ---- this warp's 4 row constants (lanes 0..3 own rows; others dup) ----
        float ru2, rv2, rew;
        {
            const int rl = iA + (lane & (ROWS_PW - 1));
            float2 er = __ldg(e2 + rl);
            float2 ar = __ldg(a2 + rl);
            float u = (er.x + ar.x) * S;
            float v = (er.y + ar.y) * S;
            ru2 = u + u;
            rv2 = v + v;
            float w = -fmaf(u, u, v * v);
            asm("ex2.approx.ftz.f32 %0, %1;" : "=f"(rew) : "f"(w));  // 2^(w_r)
        }

        float es  = 0.0f;
        int   cnt = 0;

        #pragma unroll
        for (int r = 0; r < ROWS_PW; r++) {
            const int4 m = mb[r];

            const float u2r = __shfl_sync(0xffffffffu, ru2, r);
            const float v2r = __shfl_sync(0xffffffffu, rv2, r);
            const float ewr = __shfl_sync(0xffffffffu, rew, r);

            float racc = 0.0f;
            float tt, ev;

            tt = fmaf(u2r, u4[0], w4[0]);
            tt = fmaf(v2r, v4[0], tt);
            asm("ex2.approx.ftz.f32 %0, %1;" : "=f"(ev) : "f"(tt));
            if (m.x) racc += ev;

            tt = fmaf(u2r, u4[1], w4[1]);
            tt = fmaf(v2r, v4[1], tt);
            asm("ex2.approx.ftz.f32 %0, %1;" : "=f"(ev) : "f"(tt));
            if (m.y) racc += ev;

            tt = fmaf(u2r, u4[2], w4[2]);
            tt = fmaf(v2r, v4[2], tt);
            asm("ex2.approx.ftz.f32 %0, %1;" : "=f"(ev) : "f"(tt));
            if (m.z) racc += ev;

            tt = fmaf(u2r, u4[3], w4[3]);
            tt = fmaf(v2r, v4[3], tt);
            asm("ex2.approx.ftz.f32 %0, %1;" : "=f"(ev) : "f"(tt));
            if (m.w) racc += ev;

            es = fmaf(racc, ewr, es);            // row partial * 2^(w_r)
            cnt += (m.x + m.y) + (m.z + m.w);    // mask values are 0/1
        }

        acc += (float)cnt - es;                  // masked sum of (1 - e)
    }

    #pragma unroll
    for (int off = 16; off; off >>= 1)
        acc += __shfl_xor_sync(0xffffffffu, acc, off);
    if (lane == 0) wsum[warp] = acc;
    __syncthreads();

    if (threadIdx.x == 0) {
        float s = 0.0f;
        #pragma unroll
        for (int w = 0; w < NWARPS; w++) s += wsum[w];
        atomicAdd(out, s);
    }
}

extern "C" void kernel_launch(void* const* d_in, const int* in_sizes, int n_in,
                              void* d_out, int out_size)
{
    const float* emb  = (const float*)d_in[0];
    const float* absc = (const float*)d_in[1];
    const int*   mask = (const int*)d_in[2];
    float*       out  = (float*)d_out;

    void* ctr_addr = nullptr;
    cudaGetSymbolAddress(&ctr_addr, g_ctr);
    cudaMemsetAsync(ctr_addr, 0, sizeof(unsigned int));
    cudaMemsetAsync(out, 0, sizeof(float));

    dim3 grid(10 * 148);   // persistent workers; work-stealing via g_ctr
    anchor_loss_kernel<<<grid, THREADS>>>(emb, absc, mask, out);
}

// round 14
// speedup vs baseline: 1.1784x; 1.1784x over previous
#include <cuda_runtime.h>

// AnchorLoss: sum over masked pairs of 1 - exp(-||(e_i+a_i)-(e_j+a_j)||^2 / 10)
// B=8, N=2048, D=2. Mandatory traffic: the 134MB int32 mask, read once.
//
// R14 = R11 skeleton (static grid, no queue/barriers — R13's per-item block
// convoys regressed) with two pipeline fixes:
//  - DEPTH=8, ROWS_PW=16: refill distance 7 iterations (~700+ cyc) -> DRAM
//    latency fully covered per warp
//  - statically-guarded refills (no wrap-around): R11 wasted 33% of mask LDGs
//    re-loading consumed rows; now zero waste
// Core unchanged: exponent = w_r + w_c + 2u_r*u_c + 2v_r*v_c (u=Sx, v=Sy,
// w=-(u^2+v^2)); pair = 2xFFMA+MUFU+ISETP+@P FADD; 2^(w_r) factored per row;
// row consts via SHFL from lanes 0..15; count-minus-sum accumulation.

#define BATCH    8
#define NPTS     2048
#define THREADS  128
#define NWARPS   4
#define ROWS_IT  64                      // rows per item/block
#define ROWS_PW  16                      // rows per warp
#define DEPTH    8                       // prefetch ring depth

__global__ void __launch_bounds__(THREADS, 8) anchor_loss_kernel(
    const float* __restrict__ emb,
    const float* __restrict__ abscoords,
    const int*   __restrict__ mask,
    float*       __restrict__ out)
{
    __shared__ float wsum[NWARPS];

    const int warp = threadIdx.x >> 5;
    const int lane = threadIdx.x & 31;
    const float S = 0.37982354f;         // sqrt(log2(e)/10)

    // 4096 blocks = 8 batches * 16 slabs * 32 row-groups
    const int b   = blockIdx.x >> 9;             // 512 items per batch
    const int rem = blockIdx.x & 511;
    const int j0  = (rem >> 5) * 128;            // column slab base
    const int i0  = (rem & 31) * ROWS_IT;        // row-group base

    const float2* e2 = (const float2*)emb       + (size_t)b * NPTS;
    const float2* a2 = (const float2*)abscoords + (size_t)b * NPTS;

    // ---- FIRST: deep mask prefetch (8 x LDG.128 in flight) ----
    const int iA = i0 + warp * ROWS_PW;
    const int4* mrow = reinterpret_cast<const int4*>(
        mask + ((size_t)b * NPTS + iA) * NPTS + j0) + lane;
    // row stride = NPTS ints = 512 int4

    int4 mb[DEPTH];
    #pragma unroll
    for (int d = 0; d < DEPTH; d++)
        mb[d] = __ldcs(mrow + 512 * d);

    // ---- lane's 4 slab-point constants (u, v, w = -(u^2+v^2)) — L2 hits ----
    float u4[4], v4[4], w4[4];
    {
        const float4* ee = reinterpret_cast<const float4*>(e2 + j0);
        const float4* aa = reinterpret_cast<const float4*>(a2 + j0);
        float4 ex0 = __ldg(ee + 2 * lane);
        float4 ex1 = __ldg(ee + 2 * lane + 1);
        float4 ax0 = __ldg(aa + 2 * lane);
        float4 ax1 = __ldg(aa + 2 * lane + 1);
        u4[0] = (ex0.x + ax0.x) * S;  v4[0] = (ex0.y + ax0.y) * S;
        u4[1] = (ex0.z + ax0.z) * S;  v4[1] = (ex0.w + ax0.w) * S;
        u4[2] = (ex1.x + ax1.x) * S;  v4[2] = (ex1.y + ax1.y) * S;
        u4[3] = (ex1.z + ax1.z) * S;  v4[3] = (ex1.w + ax1.w) * S;
        #pragma unroll
        for (int k = 0; k < 4; k++)
            w4[k] = -fmaf(u4[k], u4[k], v4[k] * v4[k]);
    }

    // ---- warp's 16 row constants: lanes 0..15 own one row each ----
    float ru2, rv2, rew;
    {
        const int rl = iA + (lane & (ROWS_PW - 1));
        float2 er = __ldg(e2 + rl);
        float2 ar = __ldg(a2 + rl);
        float u = (er.x + ar.x) * S;
        float v = (er.y + ar.y) * S;
        ru2 = u + u;
        rv2 = v + v;
        float w = -fmaf(u, u, v * v);
        asm("ex2.approx.ftz.f32 %0, %1;" : "=f"(rew) : "f"(w));   // 2^(w_r)
    }

    float es  = 0.0f;
    int   cnt = 0;

    #pragma unroll
    for (int r = 0; r < ROWS_PW; r++) {
        const int4 m = mb[r & (DEPTH - 1)];
        // statically-guarded refill: only rows that exist (no wasted loads)
        if (r + DEPTH < ROWS_PW)
            mb[r & (DEPTH - 1)] = __ldcs(mrow + 512 * (r + DEPTH));

        // fetch row constants from the owning lane
        const float u2r = __shfl_sync(0xffffffffu, ru2, r);
        const float v2r = __shfl_sync(0xffffffffu, rv2, r);
        const float ewr = __shfl_sync(0xffffffffu, rew, r);

        float racc = 0.0f;
        float tt, ev;

        tt = fmaf(u2r, u4[0], w4[0]);
        tt = fmaf(v2r, v4[0], tt);
        asm("ex2.approx.ftz.f32 %0, %1;" : "=f"(ev) : "f"(tt));
        if (m.x) racc += ev;

        tt = fmaf(u2r, u4[1], w4[1]);
        tt = fmaf(v2r, v4[1], tt);
        asm("ex2.approx.ftz.f32 %0, %1;" : "=f"(ev) : "f"(tt));
        if (m.y) racc += ev;

        tt = fmaf(u2r, u4[2], w4[2]);
        tt = fmaf(v2r, v4[2], tt);
        asm("ex2.approx.ftz.f32 %0, %1;" : "=f"(ev) : "f"(tt));
        if (m.z) racc += ev;

        tt = fmaf(u2r, u4[3], w4[3]);
        tt = fmaf(v2r, v4[3], tt);
        asm("ex2.approx.ftz.f32 %0, %1;" : "=f"(ev) : "f"(tt));
        if (m.w) racc += ev;

        es = fmaf(racc, ewr, es);            // row partial * 2^(w_r)
        cnt += (m.x + m.y) + (m.z + m.w);    // mask values are 0/1
    }

    float acc = (float)cnt - es;             // masked sum of (1 - e)

    #pragma unroll
    for (int off = 16; off; off >>= 1)
        acc += __shfl_xor_sync(0xffffffffu, acc, off);
    if (lane == 0) wsum[warp] = acc;
    __syncthreads();

    if (threadIdx.x == 0) {
        float s = 0.0f;
        #pragma unroll
        for (int w = 0; w < NWARPS; w++) s += wsum[w];
        atomicAdd(out, s);
    }
}

extern "C" void kernel_launch(void* const* d_in, const int* in_sizes, int n_in,
                              void* d_out, int out_size)
{
    const float* emb  = (const float*)d_in[0];
    const float* absc = (const float*)d_in[1];
    const int*   mask = (const int*)d_in[2];
    float*       out  = (float*)d_out;

    cudaMemsetAsync(out, 0, sizeof(float));

    dim3 grid(BATCH * 512);   // 4096 one-item blocks
    anchor_loss_kernel<<<grid, THREADS>>>(emb, absc, mask, out);
}